// round 10
// baseline (speedup 1.0000x reference)
#include <cuda_runtime.h>
#include <math.h>

#define BB 32
#define CC 4
#define LL 5
#define PP 230400          // 360*640
#define PP4 (PP / 4)       // 57600 float4 per channel per batch

#define DELTA_V 1.0f
#define DELTA_D 6.0f

#define BPB 25             // blocks per batch -> NBLK=800: ONE resident wave
#define TPB 256
#define ITERS 9            // 57600 / (25*256), exact
#define NBLK (BB * BPB)    // 800

// ---- scratch (allocation-free rule: __device__ globals) ----
__device__ float g_part[BB][BPB][32];        // 25 used, padded rows
__device__ unsigned short g_lab4[BB][PP4];   // 4-bit labels, 4 per quad (3.7MB)
__device__ float4 g_mean[BB][LL];            // lanes 1..5 means (for final push)
__device__ float g_validf[BB][LL];
__device__ float g_pc[BB];
__device__ float g_pdist[NBLK];
__device__ unsigned g_done;                  // last-block ticket (self-resetting)

// ================= kernel 1: per-(batch,lane) sums + counts =================
__global__ __launch_bounds__(TPB, 6) void k_accum(const int* __restrict__ tgt,
                                                  const float* __restrict__ emb) {
    const int b   = blockIdx.x / BPB;
    const int sub = blockIdx.x % BPB;
    const int4*   t4 = (const int4*)(tgt + (size_t)b * PP);
    const float4* e0 = (const float4*)(emb + (size_t)b * CC * PP);
    const float4* e1 = e0 + PP4;
    const float4* e2 = e1 + PP4;
    const float4* e3 = e2 + PP4;
    unsigned short* lrow = g_lab4[b];

    float acc[LL][CC];
    float cnt[LL];
#pragma unroll
    for (int l = 0; l < LL; l++) {
        cnt[l] = 0.f;
#pragma unroll
        for (int c = 0; c < CC; c++) acc[l][c] = 0.f;
    }

#pragma unroll 3
    for (int i = 0; i < ITERS; i++) {
        int p = (i * BPB + sub) * TPB + threadIdx.x;
        int4   tv = __ldcs(&t4[p]);      // evict-first: keep emb in L2
        float4 v0 = e0[p];
        float4 v1 = e1[p];
        float4 v2 = e2[p];
        float4 v3 = e3[p];
        lrow[p] = (unsigned short)(tv.x | (tv.y << 4) | (tv.z << 8) | (tv.w << 12));
        int   labs[4] = {tv.x, tv.y, tv.z, tv.w};
        float ex[4]   = {v0.x, v0.y, v0.z, v0.w};
        float ey[4]   = {v1.x, v1.y, v1.z, v1.w};
        float ez[4]   = {v2.x, v2.y, v2.z, v2.w};
        float ew[4]   = {v3.x, v3.y, v3.z, v3.w};
#pragma unroll
        for (int j = 0; j < 4; j++) {
            int lab = labs[j];
#pragma unroll
            for (int l = 0; l < LL; l++) {
                if (lab == l + 1) {
                    cnt[l] += 1.f;
                    acc[l][0] += ex[j]; acc[l][1] += ey[j];
                    acc[l][2] += ez[j]; acc[l][3] += ew[j];
                }
            }
        }
    }

    // deterministic block reduction: warp shuffle -> shared -> thread scan
    __shared__ float s_part[TPB / 32][25];
    const unsigned fm = 0xffffffffu;
    int wid = threadIdx.x >> 5, lid = threadIdx.x & 31;
#pragma unroll
    for (int l = 0; l < LL; l++) {
#pragma unroll
        for (int c = 0; c < CC; c++) {
            float v = acc[l][c];
#pragma unroll
            for (int o = 16; o > 0; o >>= 1) v += __shfl_xor_sync(fm, v, o);
            if (lid == 0) s_part[wid][l * CC + c] = v;
        }
        float v = cnt[l];
#pragma unroll
        for (int o = 16; o > 0; o >>= 1) v += __shfl_xor_sync(fm, v, o);
        if (lid == 0) s_part[wid][20 + l] = v;
    }
    __syncthreads();
    if (threadIdx.x < 25) {
        float s = 0.f;
#pragma unroll
        for (int w = 0; w < TPB / 32; w++) s += s_part[w][threadIdx.x];
        g_part[b][sub][threadIdx.x] = s;
    }
}

// ====== kernel 2: means prologue + per-pixel hinge + last-block combine =====
__global__ __launch_bounds__(TPB, 6) void k_dist(const float* __restrict__ emb,
                                                 float* __restrict__ out) {
    const int b   = blockIdx.x / BPB;
    const int sub = blockIdx.x % BPB;
    const int tid = threadIdx.x;
    const unsigned fm = 0xffffffffu;

    // ---- prologue: re-reduce this batch's partials (L2-resident, cheap) ----
    __shared__ float s_red[25][5];
    __shared__ float s_val[25];
    __shared__ float4 s_m[LL + 1];
    __shared__ float  s_vf[LL + 1];
    if (tid < 125) {
        int j = tid / 5, k = tid % 5;
        float s = 0.f;
#pragma unroll
        for (int ss = k; ss < BPB; ss += 5) s += g_part[b][ss][j];
        s_red[j][k] = s;
    }
    __syncthreads();
    if (tid < 25) {
        float s = 0.f;
#pragma unroll
        for (int k = 0; k < 5; k++) s += s_red[tid][k];
        s_val[tid] = s;
    }
    __syncthreads();
    if (tid < LL) {
        float cf = s_val[20 + tid];
        float v  = (cf > 1.f) ? 1.f : 0.f;
        float inv = 1.f / fmaxf(cf, 1.f);
        float4 m = make_float4(s_val[tid * 4 + 0] * inv, s_val[tid * 4 + 1] * inv,
                               s_val[tid * 4 + 2] * inv, s_val[tid * 4 + 3] * inv);
        s_m[tid + 1]  = m;
        s_vf[tid + 1] = v;
        if (sub == 0) {             // writer block publishes for the finisher
            g_mean[b][tid]   = m;
            g_validf[b][tid] = v;
        }
    }
    if (tid == 0) {
        s_m[0]  = make_float4(0.f, 0.f, 0.f, 0.f);
        s_vf[0] = 0.f;
        if (sub == 0) {
            float pc = 0.f;
#pragma unroll
            for (int l = 0; l < LL; l++) {
                float cf = s_val[20 + l];
                if (cf > 1.f) pc += cf;
            }
            g_pc[b] = pc;
        }
    }
    __syncthreads();

    // ---- main loop: per-pixel hinge pull loss ----
    const float4* e0 = (const float4*)(emb + (size_t)b * CC * PP);
    const float4* e1 = e0 + PP4;
    const float4* e2 = e1 + PP4;
    const float4* e3 = e2 + PP4;
    const unsigned short* lrow = g_lab4[b];

    float acc = 0.f;
    // reverse order: start where k_accum finished -> maximize L2 hits
#pragma unroll 3
    for (int i = ITERS - 1; i >= 0; i--) {
        int p = (i * BPB + sub) * TPB + tid;
        unsigned lab16 = lrow[p];
        float4 v0 = __ldcs(&e0[p]);
        float4 v1 = __ldcs(&e1[p]);
        float4 v2 = __ldcs(&e2[p]);
        float4 v3 = __ldcs(&e3[p]);
        float ex[4] = {v0.x, v0.y, v0.z, v0.w};
        float ey[4] = {v1.x, v1.y, v1.z, v1.w};
        float ez[4] = {v2.x, v2.y, v2.z, v2.w};
        float ew[4] = {v3.x, v3.y, v3.z, v3.w};
#pragma unroll
        for (int j = 0; j < 4; j++) {
            int lab = (lab16 >> (4 * j)) & 0xF;
            float4 m = s_m[lab];
            float d0 = ex[j] - m.x;
            float d1 = ey[j] - m.y;
            float d2 = ez[j] - m.z;
            float d3 = ew[j] - m.w;
            float sq = d0 * d0 + d1 * d1 + d2 * d2 + d3 * d3;
            float dist = sqrtf(fmaxf(sq, 1e-12f));
            float h = fmaxf(dist - DELTA_V, 0.f);
            acc += s_vf[lab] * h * h;
        }
    }

#pragma unroll
    for (int o = 16; o > 0; o >>= 1) acc += __shfl_xor_sync(fm, acc, o);
    __shared__ float s_w[TPB / 32];
    if ((tid & 31) == 0) s_w[tid >> 5] = acc;
    __syncthreads();

    __shared__ int s_last;
    if (tid == 0) {
        float s = 0.f;
#pragma unroll
        for (int w = 0; w < TPB / 32; w++) s += s_w[w];
        g_pdist[blockIdx.x] = s;
        __threadfence();
        unsigned t = atomicAdd(&g_done, 1u);
        s_last = (t == NBLK - 1) ? 1 : 0;
        if (s_last) g_done = 0;          // reset for next graph replay
    }
    __syncthreads();
    if (!s_last) return;

    // ---- finisher block: dist sum + push loss + combine ----
    __shared__ float s_d[TPB];
    float ds = 0.f;
    for (int i = tid; i < NBLK; i += TPB) ds += __ldcg(&g_pdist[i]);
    s_d[tid] = ds;
    __syncthreads();
    for (int s = TPB / 2; s > 0; s >>= 1) {
        if (tid < s) s_d[tid] += s_d[tid + s];
        __syncthreads();
    }

    __shared__ float s_var, s_has, s_pc;
    if (tid < 32) {
        int bb = tid;  // one batch per lane
        float m[LL][CC];
        float v[LL];
#pragma unroll
        for (int l = 0; l < LL; l++) {
            v[l] = __ldcg(&g_validf[bb][l]);
            float4 mm = *(const float4*)&g_mean[bb][l];
            m[l][0] = mm.x; m[l][1] = mm.y; m[l][2] = mm.z; m[l][3] = mm.w;
        }
        float psum = 0.f, np = 0.f;
#pragma unroll
        for (int i = 0; i < LL; i++) {
#pragma unroll
            for (int j = i + 1; j < LL; j++) {
                if (v[i] > 0.f && v[j] > 0.f) {
                    float sq = 0.f;
#pragma unroll
                    for (int c = 0; c < CC; c++) {
                        float d = m[i][c] - m[j][c];
                        sq += d * d;
                    }
                    float pd = sqrtf(fmaxf(sq, 1e-12f));
                    float ph = fmaxf(DELTA_D - pd, 0.f);
                    psum += ph * ph;
                    np += 1.f;
                }
            }
        }
        float var_b = (np > 0.f) ? (psum / np) : 0.f;
        float has   = (np > 0.f) ? 1.f : 0.f;
        float pc    = __ldcg(&g_pc[tid]);
#pragma unroll
        for (int o = 16; o > 0; o >>= 1) {
            var_b += __shfl_xor_sync(fm, var_b, o);
            has   += __shfl_xor_sync(fm, has, o);
            pc    += __shfl_xor_sync(fm, pc, o);
        }
        if (tid == 0) { s_var = var_b; s_has = has; s_pc = pc; }
    }
    __syncthreads();
    if (tid == 0) {
        float var_loss = (s_has > 0.f) ? (s_var / s_has) : 0.f;
        float dl = (s_pc > 0.f) ? (s_d[0] / fmaxf(s_pc, 1.f)) : 0.f;
        out[0] = dl + var_loss;
    }
}

extern "C" void kernel_launch(void* const* d_in, const int* in_sizes, int n_in,
                              void* d_out, int out_size) {
    const int*   targets = (const int*)d_in[0];
    const float* emb     = (const float*)d_in[1];
    float*       out     = (float*)d_out;

    k_accum<<<NBLK, TPB>>>(targets, emb);
    k_dist<<<NBLK, TPB>>>(emb, out);
}

// round 13
// speedup vs baseline: 1.3385x; 1.3385x over previous
#include <cuda_runtime.h>
#include <math.h>

#define BB 32
#define CC 4
#define LL 5
#define PP 230400          // 360*640
#define PP4 (PP / 4)       // 57600 float4 per channel per batch

#define DELTA_V 1.0f
#define DELTA_D 6.0f

// k_accum geometry (R8 proven: no reg cap, ~42us)
#define BPB_A 45
#define ITERS_A 5          // 57600 / (45*256)
#define NBLK_A (BB * BPB_A)   // 1440
// k_dist geometry (R9 proven: one resident wave, 26.4us)
#define BPB_D 25
#define ITERS_D 9          // 57600 / (25*256)
#define NBLK_D (BB * BPB_D)   // 800

#define TPB 256

// ---- scratch (allocation-free rule: __device__ globals) ----
__device__ float g_part[BB][BPB_A][32];      // 25 used, padded rows
__device__ unsigned short g_lab4[BB][PP4];   // 4-bit labels, 4 per quad (3.7MB)
__device__ float4 g_mean[BB][LL];            // lanes 1..5 means (for final push)
__device__ float g_validf[BB][LL];
__device__ float g_pc[BB];
__device__ float g_pdist[NBLK_D];
__device__ unsigned g_done;                  // last-block ticket (self-resetting)

// ================= kernel 1: per-(batch,lane) sums + counts =================
__global__ __launch_bounds__(TPB) void k_accum(const int* __restrict__ tgt,
                                               const float* __restrict__ emb) {
    const int b   = blockIdx.x / BPB_A;
    const int sub = blockIdx.x % BPB_A;
    const int4*   t4 = (const int4*)(tgt + (size_t)b * PP);
    const float4* e0 = (const float4*)(emb + (size_t)b * CC * PP);
    const float4* e1 = e0 + PP4;
    const float4* e2 = e1 + PP4;
    const float4* e3 = e2 + PP4;
    unsigned short* lrow = g_lab4[b];

    float acc[LL][CC];
    float cnt[LL];
#pragma unroll
    for (int l = 0; l < LL; l++) {
        cnt[l] = 0.f;
#pragma unroll
        for (int c = 0; c < CC; c++) acc[l][c] = 0.f;
    }

#pragma unroll
    for (int i = 0; i < ITERS_A; i++) {
        int p = (i * BPB_A + sub) * TPB + threadIdx.x;
        int4   tv = __ldcs(&t4[p]);      // evict-first: keep emb in L2
        float4 v0 = e0[p];
        float4 v1 = e1[p];
        float4 v2 = e2[p];
        float4 v3 = e3[p];
        lrow[p] = (unsigned short)(tv.x | (tv.y << 4) | (tv.z << 8) | (tv.w << 12));
        int   labs[4] = {tv.x, tv.y, tv.z, tv.w};
        float ex[4]   = {v0.x, v0.y, v0.z, v0.w};
        float ey[4]   = {v1.x, v1.y, v1.z, v1.w};
        float ez[4]   = {v2.x, v2.y, v2.z, v2.w};
        float ew[4]   = {v3.x, v3.y, v3.z, v3.w};
#pragma unroll
        for (int j = 0; j < 4; j++) {
            int lab = labs[j];
#pragma unroll
            for (int l = 0; l < LL; l++) {
                if (lab == l + 1) {
                    cnt[l] += 1.f;
                    acc[l][0] += ex[j]; acc[l][1] += ey[j];
                    acc[l][2] += ez[j]; acc[l][3] += ew[j];
                }
            }
        }
    }

    // deterministic block reduction: warp shuffle -> shared -> thread scan
    __shared__ float s_part[TPB / 32][25];
    const unsigned fm = 0xffffffffu;
    int wid = threadIdx.x >> 5, lid = threadIdx.x & 31;
#pragma unroll
    for (int l = 0; l < LL; l++) {
#pragma unroll
        for (int c = 0; c < CC; c++) {
            float v = acc[l][c];
#pragma unroll
            for (int o = 16; o > 0; o >>= 1) v += __shfl_xor_sync(fm, v, o);
            if (lid == 0) s_part[wid][l * CC + c] = v;
        }
        float v = cnt[l];
#pragma unroll
        for (int o = 16; o > 0; o >>= 1) v += __shfl_xor_sync(fm, v, o);
        if (lid == 0) s_part[wid][20 + l] = v;
    }
    __syncthreads();
    if (threadIdx.x < 25) {
        float s = 0.f;
#pragma unroll
        for (int w = 0; w < TPB / 32; w++) s += s_part[w][threadIdx.x];
        g_part[b][sub][threadIdx.x] = s;
    }
}

// ====== kernel 2: means prologue + per-pixel hinge + last-block combine =====
__global__ __launch_bounds__(TPB, 6) void k_dist(const float* __restrict__ emb,
                                                 float* __restrict__ out) {
    const int b   = blockIdx.x / BPB_D;
    const int sub = blockIdx.x % BPB_D;
    const int tid = threadIdx.x;
    const unsigned fm = 0xffffffffu;

    // ---- prologue: re-reduce this batch's 45 partials (L2-resident) ----
    __shared__ float s_red[25][9];
    __shared__ float s_val[25];
    __shared__ float4 s_m[LL + 1];
    __shared__ float  s_vf[LL + 1];
    if (tid < 225) {
        int j = tid / 9, k = tid % 9;
        float s = 0.f;
#pragma unroll
        for (int ss = k; ss < BPB_A; ss += 9) s += g_part[b][ss][j];
        s_red[j][k] = s;
    }
    __syncthreads();
    if (tid < 25) {
        float s = 0.f;
#pragma unroll
        for (int k = 0; k < 9; k++) s += s_red[tid][k];
        s_val[tid] = s;
    }
    __syncthreads();
    if (tid < LL) {
        float cf = s_val[20 + tid];
        float v  = (cf > 1.f) ? 1.f : 0.f;
        float inv = 1.f / fmaxf(cf, 1.f);
        float4 m = make_float4(s_val[tid * 4 + 0] * inv, s_val[tid * 4 + 1] * inv,
                               s_val[tid * 4 + 2] * inv, s_val[tid * 4 + 3] * inv);
        s_m[tid + 1]  = m;
        s_vf[tid + 1] = v;
        if (sub == 0) {             // writer block publishes for the finisher
            g_mean[b][tid]   = m;
            g_validf[b][tid] = v;
        }
    }
    if (tid == 0) {
        s_m[0]  = make_float4(0.f, 0.f, 0.f, 0.f);
        s_vf[0] = 0.f;
        if (sub == 0) {
            float pc = 0.f;
#pragma unroll
            for (int l = 0; l < LL; l++) {
                float cf = s_val[20 + l];
                if (cf > 1.f) pc += cf;
            }
            g_pc[b] = pc;
        }
    }
    __syncthreads();

    // ---- main loop: per-pixel hinge pull loss ----
    const float4* e0 = (const float4*)(emb + (size_t)b * CC * PP);
    const float4* e1 = e0 + PP4;
    const float4* e2 = e1 + PP4;
    const float4* e3 = e2 + PP4;
    const unsigned short* lrow = g_lab4[b];

    float acc = 0.f;
    // reverse order: start where k_accum finished -> maximize L2 hits
#pragma unroll 3
    for (int i = ITERS_D - 1; i >= 0; i--) {
        int p = (i * BPB_D + sub) * TPB + tid;
        unsigned lab16 = lrow[p];
        float4 v0 = __ldcs(&e0[p]);
        float4 v1 = __ldcs(&e1[p]);
        float4 v2 = __ldcs(&e2[p]);
        float4 v3 = __ldcs(&e3[p]);
        float ex[4] = {v0.x, v0.y, v0.z, v0.w};
        float ey[4] = {v1.x, v1.y, v1.z, v1.w};
        float ez[4] = {v2.x, v2.y, v2.z, v2.w};
        float ew[4] = {v3.x, v3.y, v3.z, v3.w};
#pragma unroll
        for (int j = 0; j < 4; j++) {
            int lab = (lab16 >> (4 * j)) & 0xF;
            float4 m = s_m[lab];
            float d0 = ex[j] - m.x;
            float d1 = ey[j] - m.y;
            float d2 = ez[j] - m.z;
            float d3 = ew[j] - m.w;
            float sq = d0 * d0 + d1 * d1 + d2 * d2 + d3 * d3;
            float dist = sqrtf(fmaxf(sq, 1e-12f));
            float h = fmaxf(dist - DELTA_V, 0.f);
            acc += s_vf[lab] * h * h;
        }
    }

#pragma unroll
    for (int o = 16; o > 0; o >>= 1) acc += __shfl_xor_sync(fm, acc, o);
    __shared__ float s_w[TPB / 32];
    if ((tid & 31) == 0) s_w[tid >> 5] = acc;
    __syncthreads();

    __shared__ int s_last;
    if (tid == 0) {
        float s = 0.f;
#pragma unroll
        for (int w = 0; w < TPB / 32; w++) s += s_w[w];
        g_pdist[blockIdx.x] = s;
        __threadfence();
        unsigned t = atomicAdd(&g_done, 1u);
        s_last = (t == NBLK_D - 1) ? 1 : 0;
        if (s_last) g_done = 0;          // reset for next graph replay
    }
    __syncthreads();
    if (!s_last) return;

    // ---- finisher block: dist sum + push loss + combine ----
    __shared__ float s_d[TPB];
    float ds = 0.f;
    for (int i = tid; i < NBLK_D; i += TPB) ds += __ldcg(&g_pdist[i]);
    s_d[tid] = ds;
    __syncthreads();
    for (int s = TPB / 2; s > 0; s >>= 1) {
        if (tid < s) s_d[tid] += s_d[tid + s];
        __syncthreads();
    }

    __shared__ float s_var, s_has, s_pc;
    if (tid < 32) {
        int bb = tid;  // one batch per lane
        float m[LL][CC];
        float v[LL];
#pragma unroll
        for (int l = 0; l < LL; l++) {
            v[l] = __ldcg(&g_validf[bb][l]);
            float4 mm = *(const float4*)&g_mean[bb][l];
            m[l][0] = mm.x; m[l][1] = mm.y; m[l][2] = mm.z; m[l][3] = mm.w;
        }
        float psum = 0.f, np = 0.f;
#pragma unroll
        for (int i = 0; i < LL; i++) {
#pragma unroll
            for (int j = i + 1; j < LL; j++) {
                if (v[i] > 0.f && v[j] > 0.f) {
                    float sq = 0.f;
#pragma unroll
                    for (int c = 0; c < CC; c++) {
                        float d = m[i][c] - m[j][c];
                        sq += d * d;
                    }
                    float pd = sqrtf(fmaxf(sq, 1e-12f));
                    float ph = fmaxf(DELTA_D - pd, 0.f);
                    psum += ph * ph;
                    np += 1.f;
                }
            }
        }
        float var_b = (np > 0.f) ? (psum / np) : 0.f;
        float has   = (np > 0.f) ? 1.f : 0.f;
        float pc    = __ldcg(&g_pc[tid]);
#pragma unroll
        for (int o = 16; o > 0; o >>= 1) {
            var_b += __shfl_xor_sync(fm, var_b, o);
            has   += __shfl_xor_sync(fm, has, o);
            pc    += __shfl_xor_sync(fm, pc, o);
        }
        if (tid == 0) { s_var = var_b; s_has = has; s_pc = pc; }
    }
    __syncthreads();
    if (tid == 0) {
        float var_loss = (s_has > 0.f) ? (s_var / s_has) : 0.f;
        float dl = (s_pc > 0.f) ? (s_d[0] / fmaxf(s_pc, 1.f)) : 0.f;
        out[0] = dl + var_loss;
    }
}

extern "C" void kernel_launch(void* const* d_in, const int* in_sizes, int n_in,
                              void* d_out, int out_size) {
    const int*   targets = (const int*)d_in[0];
    const float* emb     = (const float*)d_in[1];
    float*       out     = (float*)d_out;

    k_accum<<<NBLK_A, TPB>>>(targets, emb);
    k_dist<<<NBLK_D, TPB>>>(emb, out);
}

// round 14
// speedup vs baseline: 1.3430x; 1.0034x over previous
#include <cuda_runtime.h>
#include <math.h>

#define BB 32
#define CC 4
#define LL 5
#define PP 230400          // 360*640
#define PP4 (PP / 4)       // 57600 float4 per channel per batch

#define DELTA_V 1.0f
#define DELTA_D 6.0f

// k_accum geometry: single resident wave (480 blocks @ >=4 blocks/SM)
#define BPB_A 15
#define ITERS_A 15         // 57600 / (15*256)
#define NBLK_A (BB * BPB_A)   // 480
// k_dist geometry (proven): one resident wave at 6 blocks/SM
#define BPB_D 25
#define ITERS_D 9          // 57600 / (25*256)
#define NBLK_D (BB * BPB_D)   // 800

#define TPB 256

// ---- scratch (allocation-free rule: __device__ globals) ----
__device__ float g_part[BB][BPB_A][32];      // 25 used, padded rows
__device__ unsigned short g_lab4[BB][PP4];   // 4-bit labels, 4 per quad (3.7MB)
__device__ float4 g_mean[BB][LL];            // lanes 1..5 means (for final push)
__device__ float g_validf[BB][LL];
__device__ float g_pc[BB];
__device__ float g_pdist[NBLK_D];
__device__ unsigned g_done;                  // last-block ticket (self-resetting)

// ================= kernel 1: per-(batch,lane) sums + counts =================
__global__ __launch_bounds__(TPB, 4) void k_accum(const int* __restrict__ tgt,
                                                  const float* __restrict__ emb) {
    const int b   = blockIdx.x / BPB_A;
    const int sub = blockIdx.x % BPB_A;
    const int4*   t4 = (const int4*)(tgt + (size_t)b * PP);
    const float4* e0 = (const float4*)(emb + (size_t)b * CC * PP);
    const float4* e1 = e0 + PP4;
    const float4* e2 = e1 + PP4;
    const float4* e3 = e2 + PP4;
    unsigned short* lrow = g_lab4[b];

    float acc[LL][CC];
    float cnt[LL];
#pragma unroll
    for (int l = 0; l < LL; l++) {
        cnt[l] = 0.f;
#pragma unroll
        for (int c = 0; c < CC; c++) acc[l][c] = 0.f;
    }

#pragma unroll 5
    for (int i = 0; i < ITERS_A; i++) {
        int p = (i * BPB_A + sub) * TPB + threadIdx.x;
        int4   tv = __ldcs(&t4[p]);      // evict-first: keep emb in L2
        float4 v0 = e0[p];
        float4 v1 = e1[p];
        float4 v2 = e2[p];
        float4 v3 = e3[p];
        lrow[p] = (unsigned short)(tv.x | (tv.y << 4) | (tv.z << 8) | (tv.w << 12));
        int   labs[4] = {tv.x, tv.y, tv.z, tv.w};
        float ex[4]   = {v0.x, v0.y, v0.z, v0.w};
        float ey[4]   = {v1.x, v1.y, v1.z, v1.w};
        float ez[4]   = {v2.x, v2.y, v2.z, v2.w};
        float ew[4]   = {v3.x, v3.y, v3.z, v3.w};
#pragma unroll
        for (int j = 0; j < 4; j++) {
            int lab = labs[j];
#pragma unroll
            for (int l = 0; l < LL; l++) {
                if (lab == l + 1) {
                    cnt[l] += 1.f;
                    acc[l][0] += ex[j]; acc[l][1] += ey[j];
                    acc[l][2] += ez[j]; acc[l][3] += ew[j];
                }
            }
        }
    }

    // deterministic block reduction: warp shuffle -> shared -> thread scan
    __shared__ float s_part[TPB / 32][25];
    const unsigned fm = 0xffffffffu;
    int wid = threadIdx.x >> 5, lid = threadIdx.x & 31;
#pragma unroll
    for (int l = 0; l < LL; l++) {
#pragma unroll
        for (int c = 0; c < CC; c++) {
            float v = acc[l][c];
#pragma unroll
            for (int o = 16; o > 0; o >>= 1) v += __shfl_xor_sync(fm, v, o);
            if (lid == 0) s_part[wid][l * CC + c] = v;
        }
        float v = cnt[l];
#pragma unroll
        for (int o = 16; o > 0; o >>= 1) v += __shfl_xor_sync(fm, v, o);
        if (lid == 0) s_part[wid][20 + l] = v;
    }
    __syncthreads();
    if (threadIdx.x < 25) {
        float s = 0.f;
#pragma unroll
        for (int w = 0; w < TPB / 32; w++) s += s_part[w][threadIdx.x];
        g_part[b][sub][threadIdx.x] = s;
    }
}

// ====== kernel 2: means prologue + per-pixel hinge + last-block combine =====
__global__ __launch_bounds__(TPB, 6) void k_dist(const float* __restrict__ emb,
                                                 float* __restrict__ out) {
    // REVERSED block mapping: earliest-launched blocks process the data
    // k_accum touched most recently -> ride the L2 age gradient.
    const int rb  = (NBLK_D - 1) - blockIdx.x;
    const int b   = rb / BPB_D;
    const int sub = rb % BPB_D;
    const int tid = threadIdx.x;
    const unsigned fm = 0xffffffffu;

    // ---- prologue: re-reduce this batch's 15 partials (L2-resident) ----
    __shared__ float s_red[25][5];
    __shared__ float s_val[25];
    __shared__ float4 s_m[LL + 1];
    __shared__ float  s_vf[LL + 1];
    if (tid < 125) {
        int j = tid / 5, k = tid % 5;
        float s = 0.f;
#pragma unroll
        for (int ss = k; ss < BPB_A; ss += 5) s += g_part[b][ss][j];
        s_red[j][k] = s;
    }
    __syncthreads();
    if (tid < 25) {
        float s = 0.f;
#pragma unroll
        for (int k = 0; k < 5; k++) s += s_red[tid][k];
        s_val[tid] = s;
    }
    __syncthreads();
    if (tid < LL) {
        float cf = s_val[20 + tid];
        float v  = (cf > 1.f) ? 1.f : 0.f;
        float inv = 1.f / fmaxf(cf, 1.f);
        float4 m = make_float4(s_val[tid * 4 + 0] * inv, s_val[tid * 4 + 1] * inv,
                               s_val[tid * 4 + 2] * inv, s_val[tid * 4 + 3] * inv);
        s_m[tid + 1]  = m;
        s_vf[tid + 1] = v;
        if (sub == 0) {             // writer block publishes for the finisher
            g_mean[b][tid]   = m;
            g_validf[b][tid] = v;
        }
    }
    if (tid == 0) {
        s_m[0]  = make_float4(0.f, 0.f, 0.f, 0.f);
        s_vf[0] = 0.f;
        if (sub == 0) {
            float pc = 0.f;
#pragma unroll
            for (int l = 0; l < LL; l++) {
                float cf = s_val[20 + l];
                if (cf > 1.f) pc += cf;
            }
            g_pc[b] = pc;
        }
    }
    __syncthreads();

    // ---- main loop: per-pixel hinge pull loss ----
    const float4* e0 = (const float4*)(emb + (size_t)b * CC * PP);
    const float4* e1 = e0 + PP4;
    const float4* e2 = e1 + PP4;
    const float4* e3 = e2 + PP4;
    const unsigned short* lrow = g_lab4[b];

    float acc = 0.f;
    // reverse iteration order: newest lines first within the block's range
#pragma unroll 3
    for (int i = ITERS_D - 1; i >= 0; i--) {
        int p = (i * BPB_D + sub) * TPB + tid;
        unsigned lab16 = lrow[p];
        float4 v0 = __ldcs(&e0[p]);
        float4 v1 = __ldcs(&e1[p]);
        float4 v2 = __ldcs(&e2[p]);
        float4 v3 = __ldcs(&e3[p]);
        float ex[4] = {v0.x, v0.y, v0.z, v0.w};
        float ey[4] = {v1.x, v1.y, v1.z, v1.w};
        float ez[4] = {v2.x, v2.y, v2.z, v2.w};
        float ew[4] = {v3.x, v3.y, v3.z, v3.w};
#pragma unroll
        for (int j = 0; j < 4; j++) {
            int lab = (lab16 >> (4 * j)) & 0xF;
            float4 m = s_m[lab];
            float d0 = ex[j] - m.x;
            float d1 = ey[j] - m.y;
            float d2 = ez[j] - m.z;
            float d3 = ew[j] - m.w;
            float sq = d0 * d0 + d1 * d1 + d2 * d2 + d3 * d3;
            float dist = sqrtf(fmaxf(sq, 1e-12f));
            float h = fmaxf(dist - DELTA_V, 0.f);
            acc += s_vf[lab] * h * h;
        }
    }

#pragma unroll
    for (int o = 16; o > 0; o >>= 1) acc += __shfl_xor_sync(fm, acc, o);
    __shared__ float s_w[TPB / 32];
    if ((tid & 31) == 0) s_w[tid >> 5] = acc;
    __syncthreads();

    __shared__ int s_last;
    if (tid == 0) {
        float s = 0.f;
#pragma unroll
        for (int w = 0; w < TPB / 32; w++) s += s_w[w];
        g_pdist[blockIdx.x] = s;
        __threadfence();
        unsigned t = atomicAdd(&g_done, 1u);
        s_last = (t == NBLK_D - 1) ? 1 : 0;
        if (s_last) g_done = 0;          // reset for next graph replay
    }
    __syncthreads();
    if (!s_last) return;

    // ---- finisher block: dist sum + push loss + combine ----
    __shared__ float s_d[TPB];
    float ds = 0.f;
    for (int i = tid; i < NBLK_D; i += TPB) ds += __ldcg(&g_pdist[i]);
    s_d[tid] = ds;
    __syncthreads();
    for (int s = TPB / 2; s > 0; s >>= 1) {
        if (tid < s) s_d[tid] += s_d[tid + s];
        __syncthreads();
    }

    __shared__ float s_var, s_has, s_pc;
    if (tid < 32) {
        int bb = tid;  // one batch per lane
        float m[LL][CC];
        float v[LL];
#pragma unroll
        for (int l = 0; l < LL; l++) {
            v[l] = __ldcg(&g_validf[bb][l]);
            float4 mm = *(const float4*)&g_mean[bb][l];
            m[l][0] = mm.x; m[l][1] = mm.y; m[l][2] = mm.z; m[l][3] = mm.w;
        }
        float psum = 0.f, np = 0.f;
#pragma unroll
        for (int i = 0; i < LL; i++) {
#pragma unroll
            for (int j = i + 1; j < LL; j++) {
                if (v[i] > 0.f && v[j] > 0.f) {
                    float sq = 0.f;
#pragma unroll
                    for (int c = 0; c < CC; c++) {
                        float d = m[i][c] - m[j][c];
                        sq += d * d;
                    }
                    float pd = sqrtf(fmaxf(sq, 1e-12f));
                    float ph = fmaxf(DELTA_D - pd, 0.f);
                    psum += ph * ph;
                    np += 1.f;
                }
            }
        }
        float var_b = (np > 0.f) ? (psum / np) : 0.f;
        float has   = (np > 0.f) ? 1.f : 0.f;
        float pc    = __ldcg(&g_pc[tid]);
#pragma unroll
        for (int o = 16; o > 0; o >>= 1) {
            var_b += __shfl_xor_sync(fm, var_b, o);
            has   += __shfl_xor_sync(fm, has, o);
            pc    += __shfl_xor_sync(fm, pc, o);
        }
        if (tid == 0) { s_var = var_b; s_has = has; s_pc = pc; }
    }
    __syncthreads();
    if (tid == 0) {
        float var_loss = (s_has > 0.f) ? (s_var / s_has) : 0.f;
        float dl = (s_pc > 0.f) ? (s_d[0] / fmaxf(s_pc, 1.f)) : 0.f;
        out[0] = dl + var_loss;
    }
}

extern "C" void kernel_launch(void* const* d_in, const int* in_sizes, int n_in,
                              void* d_out, int out_size) {
    const int*   targets = (const int*)d_in[0];
    const float* emb     = (const float*)d_in[1];
    float*       out     = (float*)d_out;

    k_accum<<<NBLK_A, TPB>>>(targets, emb);
    k_dist<<<NBLK_D, TPB>>>(emb, out);
}

// round 15
// speedup vs baseline: 1.3469x; 1.0029x over previous
#include <cuda_runtime.h>
#include <math.h>

#define BB 32
#define CC 4
#define LL 5
#define PP 230400          // 360*640
#define PP4 (PP / 4)       // 57600 float4 per channel per batch

#define DELTA_V 1.0f
#define DELTA_D 6.0f

#define TPB 256

// k_accum: 592 blocks = 148 SMs x 4 exactly. 16 batches x19 subs + 16 x18.
#define NBLK_A 592
#define SPLIT_A 304        // 16*19
// k_dist: 888 blocks = 148 SMs x 6 exactly. 24 batches x28 subs + 8 x27.
#define NBLK_D 888
#define SPLIT_D 672        // 24*28

// ---- scratch (allocation-free rule: __device__ globals) ----
__device__ float g_part[BB][19][32];         // per-(batch,sub) partials, padded
__device__ unsigned short g_lab4[BB][PP4];   // 4-bit labels, 4 per quad (3.7MB)
__device__ float4 g_mean[BB][LL];            // lanes 1..5 means (for final push)
__device__ float g_validf[BB][LL];
__device__ float g_pc[BB];
__device__ float g_pdist[NBLK_D];
__device__ unsigned g_done;                  // last-block ticket (self-resetting)

// ================= kernel 1: per-(batch,lane) sums + counts =================
__global__ __launch_bounds__(TPB, 4) void k_accum(const int* __restrict__ tgt,
                                                  const float* __restrict__ emb) {
    int b, sub, nsub;
    if (blockIdx.x < SPLIT_A) { b = blockIdx.x / 19; sub = blockIdx.x % 19; nsub = 19; }
    else { int r = blockIdx.x - SPLIT_A; b = 16 + r / 18; sub = r % 18; nsub = 18; }

    const int4*   t4 = (const int4*)(tgt + (size_t)b * PP);
    const float4* e0 = (const float4*)(emb + (size_t)b * CC * PP);
    const float4* e1 = e0 + PP4;
    const float4* e2 = e1 + PP4;
    const float4* e3 = e2 + PP4;
    unsigned short* lrow = g_lab4[b];

    float acc[LL][CC];
    float cnt[LL];
#pragma unroll
    for (int l = 0; l < LL; l++) {
        cnt[l] = 0.f;
#pragma unroll
        for (int c = 0; c < CC; c++) acc[l][c] = 0.f;
    }

    const int stride = nsub * TPB;
#pragma unroll 4
    for (int p = sub * TPB + threadIdx.x; p < PP4; p += stride) {
        int4   tv = __ldcs(&t4[p]);      // evict-first
        float4 v0 = e0[p];
        float4 v1 = e1[p];
        float4 v2 = e2[p];
        float4 v3 = e3[p];
        lrow[p] = (unsigned short)(tv.x | (tv.y << 4) | (tv.z << 8) | (tv.w << 12));
        int   labs[4] = {tv.x, tv.y, tv.z, tv.w};
        float ex[4]   = {v0.x, v0.y, v0.z, v0.w};
        float ey[4]   = {v1.x, v1.y, v1.z, v1.w};
        float ez[4]   = {v2.x, v2.y, v2.z, v2.w};
        float ew[4]   = {v3.x, v3.y, v3.z, v3.w};
#pragma unroll
        for (int j = 0; j < 4; j++) {
            int lab = labs[j];
#pragma unroll
            for (int l = 0; l < LL; l++) {
                if (lab == l + 1) {
                    cnt[l] += 1.f;
                    acc[l][0] += ex[j]; acc[l][1] += ey[j];
                    acc[l][2] += ez[j]; acc[l][3] += ew[j];
                }
            }
        }
    }

    // deterministic block reduction: warp shuffle -> shared -> thread scan
    __shared__ float s_part[TPB / 32][25];
    const unsigned fm = 0xffffffffu;
    int wid = threadIdx.x >> 5, lid = threadIdx.x & 31;
#pragma unroll
    for (int l = 0; l < LL; l++) {
#pragma unroll
        for (int c = 0; c < CC; c++) {
            float v = acc[l][c];
#pragma unroll
            for (int o = 16; o > 0; o >>= 1) v += __shfl_xor_sync(fm, v, o);
            if (lid == 0) s_part[wid][l * CC + c] = v;
        }
        float v = cnt[l];
#pragma unroll
        for (int o = 16; o > 0; o >>= 1) v += __shfl_xor_sync(fm, v, o);
        if (lid == 0) s_part[wid][20 + l] = v;
    }
    __syncthreads();
    if (threadIdx.x < 25) {
        float s = 0.f;
#pragma unroll
        for (int w = 0; w < TPB / 32; w++) s += s_part[w][threadIdx.x];
        g_part[b][sub][threadIdx.x] = s;
    }
}

// ====== kernel 2: means prologue + per-pixel hinge + last-block combine =====
__global__ __launch_bounds__(TPB, 6) void k_dist(const float* __restrict__ emb,
                                                 float* __restrict__ out) {
    int b, sub, nsub;
    if (blockIdx.x < SPLIT_D) { b = blockIdx.x / 28; sub = blockIdx.x % 28; nsub = 28; }
    else { int r = blockIdx.x - SPLIT_D; b = 24 + r / 27; sub = r % 27; nsub = 27; }
    const int tid = threadIdx.x;
    const unsigned fm = 0xffffffffu;
    const int nsubA = (b < 16) ? 19 : 18;   // k_accum's partial count for batch b

    // ---- prologue: re-reduce this batch's partials (L2-resident) ----
    __shared__ float s_red[25][5];
    __shared__ float s_val[25];
    __shared__ float4 s_m[LL + 1];
    __shared__ float  s_vf[LL + 1];
    if (tid < 125) {
        int j = tid / 5, k = tid % 5;
        float s = 0.f;
        for (int ss = k; ss < nsubA; ss += 5) s += g_part[b][ss][j];
        s_red[j][k] = s;
    }
    __syncthreads();
    if (tid < 25) {
        float s = 0.f;
#pragma unroll
        for (int k = 0; k < 5; k++) s += s_red[tid][k];
        s_val[tid] = s;
    }
    __syncthreads();
    if (tid < LL) {
        float cf = s_val[20 + tid];
        float v  = (cf > 1.f) ? 1.f : 0.f;
        float inv = 1.f / fmaxf(cf, 1.f);
        float4 m = make_float4(s_val[tid * 4 + 0] * inv, s_val[tid * 4 + 1] * inv,
                               s_val[tid * 4 + 2] * inv, s_val[tid * 4 + 3] * inv);
        s_m[tid + 1]  = m;
        s_vf[tid + 1] = v;
        if (sub == 0) {             // writer block publishes for the finisher
            g_mean[b][tid]   = m;
            g_validf[b][tid] = v;
        }
    }
    if (tid == 0) {
        s_m[0]  = make_float4(0.f, 0.f, 0.f, 0.f);
        s_vf[0] = 0.f;
        if (sub == 0) {
            float pc = 0.f;
#pragma unroll
            for (int l = 0; l < LL; l++) {
                float cf = s_val[20 + l];
                if (cf > 1.f) pc += cf;
            }
            g_pc[b] = pc;
        }
    }
    __syncthreads();

    // ---- main loop: per-pixel hinge pull loss ----
    const float4* e0 = (const float4*)(emb + (size_t)b * CC * PP);
    const float4* e1 = e0 + PP4;
    const float4* e2 = e1 + PP4;
    const float4* e3 = e2 + PP4;
    const unsigned short* lrow = g_lab4[b];

    float acc = 0.f;
    const int stride = nsub * TPB;
#pragma unroll 4
    for (int p = sub * TPB + tid; p < PP4; p += stride) {
        unsigned lab16 = lrow[p];
        float4 v0 = __ldcs(&e0[p]);
        float4 v1 = __ldcs(&e1[p]);
        float4 v2 = __ldcs(&e2[p]);
        float4 v3 = __ldcs(&e3[p]);
        float ex[4] = {v0.x, v0.y, v0.z, v0.w};
        float ey[4] = {v1.x, v1.y, v1.z, v1.w};
        float ez[4] = {v2.x, v2.y, v2.z, v2.w};
        float ew[4] = {v3.x, v3.y, v3.z, v3.w};
#pragma unroll
        for (int j = 0; j < 4; j++) {
            int lab = (lab16 >> (4 * j)) & 0xF;
            float4 m = s_m[lab];
            float d0 = ex[j] - m.x;
            float d1 = ey[j] - m.y;
            float d2 = ez[j] - m.z;
            float d3 = ew[j] - m.w;
            float sq = d0 * d0 + d1 * d1 + d2 * d2 + d3 * d3;
            float dist = sqrtf(fmaxf(sq, 1e-12f));
            float h = fmaxf(dist - DELTA_V, 0.f);
            acc += s_vf[lab] * h * h;
        }
    }

#pragma unroll
    for (int o = 16; o > 0; o >>= 1) acc += __shfl_xor_sync(fm, acc, o);
    __shared__ float s_w[TPB / 32];
    if ((tid & 31) == 0) s_w[tid >> 5] = acc;
    __syncthreads();

    __shared__ int s_last;
    if (tid == 0) {
        float s = 0.f;
#pragma unroll
        for (int w = 0; w < TPB / 32; w++) s += s_w[w];
        g_pdist[blockIdx.x] = s;
        __threadfence();
        unsigned t = atomicAdd(&g_done, 1u);
        s_last = (t == NBLK_D - 1) ? 1 : 0;
        if (s_last) g_done = 0;          // reset for next graph replay
    }
    __syncthreads();
    if (!s_last) return;

    // ---- finisher block: dist sum + push loss + combine ----
    __shared__ float s_d[TPB];
    float ds = 0.f;
    for (int i = tid; i < NBLK_D; i += TPB) ds += __ldcg(&g_pdist[i]);
    s_d[tid] = ds;
    __syncthreads();
    for (int s = TPB / 2; s > 0; s >>= 1) {
        if (tid < s) s_d[tid] += s_d[tid + s];
        __syncthreads();
    }

    __shared__ float s_var, s_has, s_pc;
    if (tid < 32) {
        int bb = tid;  // one batch per lane
        float m[LL][CC];
        float v[LL];
#pragma unroll
        for (int l = 0; l < LL; l++) {
            v[l] = __ldcg(&g_validf[bb][l]);
            float4 mm = *(const float4*)&g_mean[bb][l];
            m[l][0] = mm.x; m[l][1] = mm.y; m[l][2] = mm.z; m[l][3] = mm.w;
        }
        float psum = 0.f, np = 0.f;
#pragma unroll
        for (int i = 0; i < LL; i++) {
#pragma unroll
            for (int j = i + 1; j < LL; j++) {
                if (v[i] > 0.f && v[j] > 0.f) {
                    float sq = 0.f;
#pragma unroll
                    for (int c = 0; c < CC; c++) {
                        float d = m[i][c] - m[j][c];
                        sq += d * d;
                    }
                    float pd = sqrtf(fmaxf(sq, 1e-12f));
                    float ph = fmaxf(DELTA_D - pd, 0.f);
                    psum += ph * ph;
                    np += 1.f;
                }
            }
        }
        float var_b = (np > 0.f) ? (psum / np) : 0.f;
        float has   = (np > 0.f) ? 1.f : 0.f;
        float pc    = __ldcg(&g_pc[tid]);
#pragma unroll
        for (int o = 16; o > 0; o >>= 1) {
            var_b += __shfl_xor_sync(fm, var_b, o);
            has   += __shfl_xor_sync(fm, has, o);
            pc    += __shfl_xor_sync(fm, pc, o);
        }
        if (tid == 0) { s_var = var_b; s_has = has; s_pc = pc; }
    }
    __syncthreads();
    if (tid == 0) {
        float var_loss = (s_has > 0.f) ? (s_var / s_has) : 0.f;
        float dl = (s_pc > 0.f) ? (s_d[0] / fmaxf(s_pc, 1.f)) : 0.f;
        out[0] = dl + var_loss;
    }
}

extern "C" void kernel_launch(void* const* d_in, const int* in_sizes, int n_in,
                              void* d_out, int out_size) {
    const int*   targets = (const int*)d_in[0];
    const float* emb     = (const float*)d_in[1];
    float*       out     = (float*)d_out;

    k_accum<<<NBLK_A, TPB>>>(targets, emb);
    k_dist<<<NBLK_D, TPB>>>(emb, out);
}